// round 3
// baseline (speedup 1.0000x reference)
#include <cuda_runtime.h>
#include <math.h>

#define H_ 64
#define W_ 64
#define DIM 384
#define NHEADS 12
#define HDIM 32
#define WSZ 7
#define NTOK 49
#define NWIN 400
#define TOK 19600
#define BATCH 4
#define HW 4096
#define HID 1536
#define ATTN_SCALE 0.17677669529663689f
#define LN_EPS 1e-5f

// ---------------- aliased scratch (device globals; lifetimes disjoint) ----------
// bufA: xn (LN1 out, 19600x384) -> att (19600x384) -> ln2 (16384x384)
// bufB: qkv (19600x1152) -> x1 (16384x384) -> h1 (16384x1536)
// bufC: x2 (conv+BN out, 16384x384), live until final residual
__device__ float g_bufA[TOK * DIM];
__device__ float g_bufB[BATCH * HW * HID];
__device__ float g_bufC[BATCH * HW * DIM];

// ---------------- block reduce (128 threads, 2 values) ----------------
__device__ __forceinline__ void blockReduce2_128(float& s, float& q) {
    __shared__ float sh[8];
    int lane = threadIdx.x & 31, warp = threadIdx.x >> 5;
    #pragma unroll
    for (int o = 16; o > 0; o >>= 1) {
        s += __shfl_down_sync(0xffffffffu, s, o);
        q += __shfl_down_sync(0xffffffffu, q, o);
    }
    if (lane == 0) { sh[warp] = s; sh[4 + warp] = q; }
    __syncthreads();
    if (threadIdx.x == 0) {
        float a = 0.f, b = 0.f;
        #pragma unroll
        for (int i = 0; i < 4; i++) { a += sh[i]; b += sh[4 + i]; }
        sh[0] = a; sh[4] = b;
    }
    __syncthreads();
    s = sh[0]; q = sh[4];
    __syncthreads();
}

// ---------------- LN1 with window-partition gather ----------------
__global__ void ln1_win_kernel(const float* __restrict__ x,
                               const float* __restrict__ g,
                               const float* __restrict__ b) {
    int t = blockIdx.x;
    int w = t / NTOK, n = t % NTOK;
    int bb = w / 100;
    int wh = (w / 10) % 10;
    int ww = w % 10;
    int r = wh * WSZ + n / WSZ;
    int c = ww * WSZ + n % WSZ;
    float* out = g_bufA + (size_t)t * DIM;
    if (r >= H_ || c >= W_) {   // padded token: input zeros -> LN output = bias
        for (int ch = threadIdx.x; ch < DIM; ch += 128) out[ch] = b[ch];
        return;
    }
    const float* row = x + ((size_t)bb * HW + (size_t)r * W_ + c) * DIM;
    float v0 = row[threadIdx.x];
    float v1 = row[threadIdx.x + 128];
    float v2 = row[threadIdx.x + 256];
    float s = v0 + v1 + v2;
    float q = v0 * v0 + v1 * v1 + v2 * v2;
    blockReduce2_128(s, q);
    float mean = s * (1.f / DIM);
    float var = q * (1.f / DIM) - mean * mean;
    float rs = rsqrtf(var + LN_EPS);
    int ch = threadIdx.x;
    out[ch]       = (v0 - mean) * rs * g[ch]       + b[ch];
    out[ch + 128] = (v1 - mean) * rs * g[ch + 128] + b[ch + 128];
    out[ch + 256] = (v2 - mean) * rs * g[ch + 256] + b[ch + 256];
}

// ---------------- generic LN (contiguous tokens) ----------------
__global__ void ln_kernel(const float* __restrict__ in,
                          const float* __restrict__ g,
                          const float* __restrict__ b,
                          float* __restrict__ out) {
    int t = blockIdx.x;
    const float* row = in + (size_t)t * DIM;
    float v0 = row[threadIdx.x];
    float v1 = row[threadIdx.x + 128];
    float v2 = row[threadIdx.x + 256];
    float s = v0 + v1 + v2;
    float q = v0 * v0 + v1 * v1 + v2 * v2;
    blockReduce2_128(s, q);
    float mean = s * (1.f / DIM);
    float var = q * (1.f / DIM) - mean * mean;
    float rs = rsqrtf(var + LN_EPS);
    float* o = out + (size_t)t * DIM;
    int ch = threadIdx.x;
    o[ch]       = (v0 - mean) * rs * g[ch]       + b[ch];
    o[ch + 128] = (v1 - mean) * rs * g[ch + 128] + b[ch + 128];
    o[ch + 256] = (v2 - mean) * rs * g[ch + 256] + b[ch + 256];
}

// ---------------- 128x128x16 fp32 GEMM, 8x8 per thread, fused epilogues -------
// EPI 0: C = v                                   (qkv)
// EPI 1: un-window + residual scatter            (proj)
// EPI 2: C = gelu_exact(v)                       (fc1)
// EPI 3: C = v + res                             (fc2 -> d_out)
#define BM 128
#define BN 128
#define BK 16
template <int EPI>
__global__ __launch_bounds__(256)
void sgemm_kernel(const float* __restrict__ A,
                  const float* __restrict__ B,
                  const float* __restrict__ bias,
                  const float* __restrict__ res,
                  float* __restrict__ C,
                  int M, int N, int K) {
    __shared__ float As[BK][BM + 4];
    __shared__ float Bs[BK][BN];
    int tid = threadIdx.x;
    int tx = tid & 15;          // 16 col-groups of 8
    int ty = tid >> 4;          // 16 row-groups of 8
    int row0 = blockIdx.y * BM;
    int col0 = blockIdx.x * BN;
    float acc[8][8] = {};

    for (int k0 = 0; k0 < K; k0 += BK) {
        // A tile 128x16 (transposed into smem), float4 global loads
        #pragma unroll
        for (int i = 0; i < 2; i++) {
            int s = tid + i * 256;        // 512 float4 slots
            int ar = s >> 2;
            int kv = (s & 3) * 4;
            float4 v = make_float4(0.f, 0.f, 0.f, 0.f);
            int gr = row0 + ar;
            if (gr < M) v = *(const float4*)(A + (size_t)gr * K + k0 + kv);
            As[kv + 0][ar] = v.x;
            As[kv + 1][ar] = v.y;
            As[kv + 2][ar] = v.z;
            As[kv + 3][ar] = v.w;
        }
        // B tile 16x128, float4 both sides (N always multiple of 128 here)
        #pragma unroll
        for (int i = 0; i < 2; i++) {
            int s = tid + i * 256;
            int br = s >> 5;
            int bc = (s & 31) * 4;
            *(float4*)(&Bs[br][bc]) =
                *(const float4*)(B + (size_t)(k0 + br) * N + col0 + bc);
        }
        __syncthreads();
        #pragma unroll
        for (int kk = 0; kk < BK; kk++) {
            float a[8], bv[8];
            *(float4*)(a)      = *(const float4*)(&As[kk][ty * 8]);
            *(float4*)(a + 4)  = *(const float4*)(&As[kk][ty * 8 + 4]);
            *(float4*)(bv)     = *(const float4*)(&Bs[kk][tx * 8]);
            *(float4*)(bv + 4) = *(const float4*)(&Bs[kk][tx * 8 + 4]);
            #pragma unroll
            for (int i = 0; i < 8; i++)
                #pragma unroll
                for (int j = 0; j < 8; j++)
                    acc[i][j] += a[i] * bv[j];
        }
        __syncthreads();
    }

    #pragma unroll
    for (int i = 0; i < 8; i++) {
        int r = row0 + ty * 8 + i;
        if (r >= M) break;
        // precompute scatter base for EPI 1
        size_t obase = 0;
        bool valid = true;
        if (EPI == 1) {
            int w = r / NTOK, n = r % NTOK;
            int bb = w / 100;
            int wh = (w / 10) % 10;
            int ww = w % 10;
            int rr = wh * WSZ + n / WSZ;
            int cc = ww * WSZ + n % WSZ;
            valid = (rr < H_ && cc < W_);
            if (valid) obase = ((size_t)bb * HW + (size_t)rr * W_ + cc) * DIM;
        }
        #pragma unroll
        for (int j = 0; j < 8; j++) {
            int c = col0 + tx * 8 + j;
            float v = acc[i][j] + bias[c];
            if (EPI == 0) {
                C[(size_t)r * N + c] = v;
            } else if (EPI == 1) {
                if (valid) C[obase + c] = res[obase + c] + v;
            } else if (EPI == 2) {
                C[(size_t)r * N + c] = 0.5f * v * (1.f + erff(v * 0.70710678118654752f));
            } else {
                C[(size_t)r * N + c] = v + res[(size_t)r * N + c];
            }
        }
    }
}

// ---------------- attention: one block per (window, head) ----------------
__global__ void attn_kernel(const float* __restrict__ attn_bias) {
    int w = blockIdx.x / NHEADS;
    int h = blockIdx.x % NHEADS;
    __shared__ float qs[NTOK][HDIM + 1];
    __shared__ float ks[NTOK][HDIM + 1];
    __shared__ float vs[NTOK][HDIM + 1];
    __shared__ float sc[NTOK][NTOK + 1];
    __shared__ float bsm[NTOK];
    int tid = threadIdx.x;

    for (int i = tid; i < NTOK * HDIM; i += 128) {
        int n = i / HDIM, d = i % HDIM;
        const float* base = g_bufB + ((size_t)w * NTOK + n) * (3 * DIM) + h * (3 * HDIM);
        qs[n][d] = base[d];
        ks[n][d] = base[HDIM + d];
        vs[n][d] = base[2 * HDIM + d];
    }
    if (tid < NTOK) bsm[tid] = attn_bias[h * NTOK + tid];
    __syncthreads();

    for (int i = tid; i < NTOK * NTOK; i += 128) {
        int n = i / NTOK, m = i % NTOK;
        float s = 0.f;
        #pragma unroll
        for (int d = 0; d < HDIM; d++) s += qs[n][d] * ks[m][d];
        int dr = abs(n / WSZ - m / WSZ);
        int dc = abs(n % WSZ - m % WSZ);
        sc[n][m] = s * ATTN_SCALE + bsm[dr * WSZ + dc];
    }
    __syncthreads();

    if (tid < NTOK) {
        float mx = -1e30f;
        #pragma unroll 7
        for (int m = 0; m < NTOK; m++) mx = fmaxf(mx, sc[tid][m]);
        float sum = 0.f;
        #pragma unroll 7
        for (int m = 0; m < NTOK; m++) {
            float e = expf(sc[tid][m] - mx);
            sc[tid][m] = e;
            sum += e;
        }
        float inv = 1.f / sum;
        #pragma unroll 7
        for (int m = 0; m < NTOK; m++) sc[tid][m] *= inv;
    }
    __syncthreads();

    for (int i = tid; i < NTOK * HDIM; i += 128) {
        int n = i / HDIM, d = i % HDIM;
        float s = 0.f;
        #pragma unroll 7
        for (int m = 0; m < NTOK; m++) s += sc[n][m] * vs[m][d];
        g_bufA[((size_t)w * NTOK + n) * DIM + h * HDIM + d] = s;
    }
}

// ---------------- depthwise 3x3 conv + BN (channel-last) ----------------
__global__ void conv_bn_kernel(const float* __restrict__ w9,
                               const float* __restrict__ bn_g,
                               const float* __restrict__ bn_b,
                               const float* __restrict__ bn_mean,
                               const float* __restrict__ bn_var) {
    int p = blockIdx.x;               // b*HW + pos
    int bb = p >> 12;
    int pos = p & 4095;
    int r = pos >> 6, c = pos & 63;
    const float* base = g_bufB + (size_t)bb * HW * DIM;   // x1 lives in bufB
    for (int ch = threadIdx.x; ch < DIM; ch += 128) {
        float s = 0.f;
        #pragma unroll
        for (int kh = 0; kh < 3; kh++) {
            int rr = r + kh - 1;
            if (rr < 0 || rr >= H_) continue;
            #pragma unroll
            for (int kw = 0; kw < 3; kw++) {
                int cc = c + kw - 1;
                if (cc < 0 || cc >= W_) continue;
                s += base[((size_t)rr * W_ + cc) * DIM + ch] * w9[ch * 9 + kh * 3 + kw];
            }
        }
        float o = (s - bn_mean[ch]) * rsqrtf(bn_var[ch] + LN_EPS) * bn_g[ch] + bn_b[ch];
        g_bufC[(size_t)p * DIM + ch] = o;
    }
}

// ---------------- launch ----------------
extern "C" void kernel_launch(void* const* d_in, const int* in_sizes, int n_in,
                              void* d_out, int out_size) {
    const float* x       = (const float*)d_in[0];
    const float* ln1_g   = (const float*)d_in[1];
    const float* ln1_b   = (const float*)d_in[2];
    const float* qkv_w   = (const float*)d_in[3];
    const float* qkv_b   = (const float*)d_in[4];
    const float* proj_w  = (const float*)d_in[5];
    const float* proj_b  = (const float*)d_in[6];
    const float* attn_b  = (const float*)d_in[7];
    const float* conv_w  = (const float*)d_in[8];
    const float* bn_g    = (const float*)d_in[9];
    const float* bn_b    = (const float*)d_in[10];
    const float* bn_mean = (const float*)d_in[11];
    const float* bn_var  = (const float*)d_in[12];
    const float* ln2_g   = (const float*)d_in[13];
    const float* ln2_b   = (const float*)d_in[14];
    const float* fc1_w   = (const float*)d_in[15];
    const float* fc1_b   = (const float*)d_in[16];
    const float* fc2_w   = (const float*)d_in[17];
    const float* fc2_b   = (const float*)d_in[18];
    float* out = (float*)d_out;

    float *pA, *pB, *pC;
    cudaGetSymbolAddress((void**)&pA, g_bufA);
    cudaGetSymbolAddress((void**)&pB, g_bufB);
    cudaGetSymbolAddress((void**)&pC, g_bufC);

    // 1. LN1 + window partition -> bufA (xn)
    ln1_win_kernel<<<TOK, 128>>>(x, ln1_g, ln1_b);

    // 2. QKV GEMM: (19600,384)@(384,1152) -> bufB (qkv)
    {
        dim3 grid((3 * DIM) / BN, (TOK + BM - 1) / BM);
        sgemm_kernel<0><<<grid, 256>>>(pA, qkv_w, qkv_b, nullptr, pB, TOK, 3 * DIM, DIM);
    }

    // 3. attention -> bufA (att)
    attn_kernel<<<NWIN * NHEADS, 128>>>(attn_b);

    // 4. proj GEMM + fused un-window + residual -> bufB (x1)
    {
        dim3 grid(DIM / BN, (TOK + BM - 1) / BM);
        sgemm_kernel<1><<<grid, 256>>>(pA, proj_w, proj_b, x, pB, TOK, DIM, DIM);
    }

    // 5. depthwise conv + BN -> bufC (x2)
    conv_bn_kernel<<<BATCH * HW, 128>>>(conv_w, bn_g, bn_b, bn_mean, bn_var);

    // 6. LN2: bufC -> bufA (ln2)
    ln_kernel<<<BATCH * HW, 128>>>(pC, ln2_g, ln2_b, pA);

    // 7. FC1 + exact GELU: (16384,384)@(384,1536) -> bufB (h1)
    {
        dim3 grid(HID / BN, (BATCH * HW + BM - 1) / BM);
        sgemm_kernel<2><<<grid, 256>>>(pA, fc1_w, fc1_b, nullptr, pB, BATCH * HW, HID, DIM);
    }

    // 8. FC2 + residual -> d_out: (16384,1536)@(1536,384)
    {
        dim3 grid(DIM / BN, (BATCH * HW + BM - 1) / BM);
        sgemm_kernel<3><<<grid, 256>>>(pB, fc2_w, fc2_b, pC, out, BATCH * HW, DIM, HID);
    }
}

// round 6
// speedup vs baseline: 2.4262x; 2.4262x over previous
#include <cuda_runtime.h>
#include <math.h>
#include <stdint.h>

#define H_ 64
#define W_ 64
#define DIM 384
#define NHEADS 12
#define HDIM 32
#define WSZ 7
#define NTOK 49
#define NWIN 400
#define TOK 19600
#define BATCH 4
#define HW 4096
#define HID 1536
#define ATTN_SCALE 0.17677669529663689f
#define LN_EPS 1e-5f

// ---------------- scratch (device globals) ----------------
// bufA: xn (19600x384) -> att (19600x384) -> ln2 (16384x384)
// bufB: qkv (19600x1152) -> x1 (16384x384) -> h1 (16384x1536)
// bufC: x2 (conv+BN out), live until final residual
__device__ float g_bufA[TOK * DIM];
__device__ float g_bufB[BATCH * HW * HID];
__device__ float g_bufC[BATCH * HW * DIM];
// transposed weights: qkv(1152x384) proj(384x384) fc1(1536x384) fc2(384x1536)
#define WT_QKV_OFF 0
#define WT_PROJ_OFF (1152*384)
#define WT_FC1_OFF  (WT_PROJ_OFF + 384*384)
#define WT_FC2_OFF  (WT_FC1_OFF + 1536*384)
__device__ float g_wt[WT_FC2_OFF + 384*1536];

// ---------------- cp.async helpers ----------------
__device__ __forceinline__ uint32_t smem_u32(const void* p) {
    uint32_t a;
    asm("{ .reg .u64 t; cvta.to.shared.u64 t, %1; cvt.u32.u64 %0, t; }" : "=r"(a) : "l"(p));
    return a;
}
__device__ __forceinline__ void cp_async16(uint32_t dst, const void* src, int srcbytes) {
    asm volatile("cp.async.cg.shared.global [%0], [%1], 16, %2;"
                 :: "r"(dst), "l"(src), "r"(srcbytes));
}
#define CP_COMMIT() asm volatile("cp.async.commit_group;" ::: "memory")
#define CP_WAIT1()  asm volatile("cp.async.wait_group 1;" ::: "memory")
#define CP_WAIT0()  asm volatile("cp.async.wait_group 0;" ::: "memory")

__device__ __forceinline__ void mma_tf32(float* c, const uint32_t* a, const uint32_t* b) {
    asm volatile(
        "mma.sync.aligned.m16n8k8.row.col.f32.tf32.tf32.f32 "
        "{%0,%1,%2,%3}, {%4,%5,%6,%7}, {%8,%9}, {%0,%1,%2,%3};"
        : "+f"(c[0]), "+f"(c[1]), "+f"(c[2]), "+f"(c[3])
        : "r"(a[0]), "r"(a[1]), "r"(a[2]), "r"(a[3]), "r"(b[0]), "r"(b[1]));
}

// ---------------- tensor-core tf32 GEMM via mma.sync ----------------
// C(M,N) = A(M,K) @ WT(N,K)^T + bias, fused epilogues:
// EPI 0: C = v          EPI 1: un-window + residual scatter
// EPI 2: gelu(v)        EPI 3: v + res
#define BM 128
#define BN 128
#define BK 16
#define PADK 20   // floats per smem row (bank-conflict-free fragment loads)
template <int EPI>
__global__ __launch_bounds__(256)
void mma_gemm(const float* __restrict__ A, const float* __restrict__ WT,
              const float* __restrict__ bias, const float* __restrict__ res,
              float* __restrict__ C, int M, int N, int K) {
    __shared__ float As[2][BM * PADK];
    __shared__ float Bs[2][BN * PADK];
    int tid = threadIdx.x;
    int lane = tid & 31, wid = tid >> 5;
    int wm = wid & 1, wn = wid >> 1;        // warp grid 2 (M) x 4 (N)
    int row0 = blockIdx.y * BM, col0 = blockIdx.x * BN;
    int g4 = lane >> 2;    // groupID (0..7)
    int t4 = lane & 3;     // thread-in-group (0..3)

    float acc[4][4][4] = {};                 // [mi][nj][reg]

    uint32_t sA[2] = { smem_u32(As[0]), smem_u32(As[1]) };
    uint32_t sB[2] = { smem_u32(Bs[0]), smem_u32(Bs[1]) };

    int nk = K / BK;

    // --- staging: 128 rows x 16 floats each for A and B ---
    // each thread: 2 chunks of 16B for A, 2 for B
    int sr = tid >> 2;         // row 0..63 (two passes of 64)
    int sc = tid & 3;          // 16B chunk 0..3
    #define STAGE(buf, k0) do { \
        int _k0 = (k0); \
        _Pragma("unroll") \
        for (int i = 0; i < 2; i++) { \
            int r = sr + i * 64; \
            int gr = row0 + r; \
            uint32_t d = sA[buf] + (uint32_t)(r * PADK + sc * 4) * 4u; \
            cp_async16(d, A + (size_t)gr * K + _k0 + sc * 4, gr < M ? 16 : 0); \
        } \
        _Pragma("unroll") \
        for (int i = 0; i < 2; i++) { \
            int r = sr + i * 64; \
            uint32_t d = sB[buf] + (uint32_t)(r * PADK + sc * 4) * 4u; \
            cp_async16(d, WT + (size_t)(col0 + r) * K + _k0 + sc * 4, 16); \
        } \
        CP_COMMIT(); \
    } while (0)

    STAGE(0, 0);
    for (int t = 0; t < nk; t++) {
        int buf = t & 1;
        if (t + 1 < nk) { STAGE(buf ^ 1, (t + 1) * BK); CP_WAIT1(); }
        else            { CP_WAIT0(); }
        __syncthreads();

        const float* as = As[buf];
        const float* bs = Bs[buf];
        #pragma unroll
        for (int kk = 0; kk < BK; kk += 8) {
            uint32_t af[4][4], bf[4][2];
            #pragma unroll
            for (int mi = 0; mi < 4; mi++) {
                int m = wm * 64 + mi * 16 + g4;
                af[mi][0] = __float_as_uint(as[m * PADK + kk + t4]);
                af[mi][1] = __float_as_uint(as[(m + 8) * PADK + kk + t4]);
                af[mi][2] = __float_as_uint(as[m * PADK + kk + t4 + 4]);
                af[mi][3] = __float_as_uint(as[(m + 8) * PADK + kk + t4 + 4]);
            }
            #pragma unroll
            for (int nj = 0; nj < 4; nj++) {
                int n = wn * 32 + nj * 8 + g4;
                bf[nj][0] = __float_as_uint(bs[n * PADK + kk + t4]);
                bf[nj][1] = __float_as_uint(bs[n * PADK + kk + t4 + 4]);
            }
            #pragma unroll
            for (int mi = 0; mi < 4; mi++)
                #pragma unroll
                for (int nj = 0; nj < 4; nj++)
                    mma_tf32(acc[mi][nj], af[mi], bf[nj]);
        }
        __syncthreads();
    }

    // ---------------- epilogue ----------------
    #pragma unroll
    for (int mi = 0; mi < 4; mi++) {
        #pragma unroll
        for (int half = 0; half < 2; half++) {
            int r = row0 + wm * 64 + mi * 16 + g4 + half * 8;
            if (r >= M) continue;
            size_t obase = 0;
            bool valid = true;
            if (EPI == 1) {
                int w = r / NTOK, n = r % NTOK;
                int bb = w / 100, wh = (w / 10) % 10, ww = w % 10;
                int rr = wh * WSZ + n / WSZ;
                int cc = ww * WSZ + n % WSZ;
                valid = (rr < H_) && (cc < W_);
                if (valid) obase = ((size_t)bb * HW + (size_t)rr * W_ + cc) * DIM;
            }
            #pragma unroll
            for (int nj = 0; nj < 4; nj++) {
                int cn = col0 + wn * 32 + nj * 8 + 2 * t4;
                float v0 = acc[mi][nj][half * 2 + 0] + bias[cn];
                float v1 = acc[mi][nj][half * 2 + 1] + bias[cn + 1];
                if (EPI == 0) {
                    *(float2*)(C + (size_t)r * N + cn) = make_float2(v0, v1);
                } else if (EPI == 1) {
                    if (valid) {
                        float2 rr2 = *(const float2*)(res + obase + cn);
                        *(float2*)(C + obase + cn) = make_float2(v0 + rr2.x, v1 + rr2.y);
                    }
                } else if (EPI == 2) {
                    v0 = 0.5f * v0 * (1.f + erff(v0 * 0.70710678118654752f));
                    v1 = 0.5f * v1 * (1.f + erff(v1 * 0.70710678118654752f));
                    *(float2*)(C + (size_t)r * N + cn) = make_float2(v0, v1);
                } else {
                    float2 rr2 = *(const float2*)(res + (size_t)r * N + cn);
                    *(float2*)(C + (size_t)r * N + cn) = make_float2(v0 + rr2.x, v1 + rr2.y);
                }
            }
        }
    }
}

// ---------------- weight transpose: WT(N,K) <- W(K,N) ----------------
__global__ void transpose_kernel(const float* __restrict__ W, float* __restrict__ WT,
                                 int K, int N) {
    __shared__ float t[32][33];
    int n0 = blockIdx.x * 32, k0 = blockIdx.y * 32;
    int tx = threadIdx.x, ty = threadIdx.y;
    #pragma unroll
    for (int i = 0; i < 32; i += 8)
        t[ty + i][tx] = W[(size_t)(k0 + ty + i) * N + n0 + tx];
    __syncthreads();
    #pragma unroll
    for (int i = 0; i < 32; i += 8)
        WT[(size_t)(n0 + ty + i) * K + k0 + tx] = t[tx][ty + i];
}

// ---------------- block reduce (128 threads) ----------------
__device__ __forceinline__ void blockReduce2_128(float& s, float& q) {
    __shared__ float sh[8];
    int lane = threadIdx.x & 31, warp = threadIdx.x >> 5;
    #pragma unroll
    for (int o = 16; o > 0; o >>= 1) {
        s += __shfl_down_sync(0xffffffffu, s, o);
        q += __shfl_down_sync(0xffffffffu, q, o);
    }
    if (lane == 0) { sh[warp] = s; sh[4 + warp] = q; }
    __syncthreads();
    if (threadIdx.x == 0) {
        float a = 0.f, b = 0.f;
        #pragma unroll
        for (int i = 0; i < 4; i++) { a += sh[i]; b += sh[4 + i]; }
        sh[0] = a; sh[4] = b;
    }
    __syncthreads();
    s = sh[0]; q = sh[4];
    __syncthreads();
}

// ---------------- LN1 with window-partition gather ----------------
__global__ void ln1_win_kernel(const float* __restrict__ x,
                               const float* __restrict__ g,
                               const float* __restrict__ b) {
    int t = blockIdx.x;
    int w = t / NTOK, n = t % NTOK;
    int bb = w / 100, wh = (w / 10) % 10, ww = w % 10;
    int r = wh * WSZ + n / WSZ;
    int c = ww * WSZ + n % WSZ;
    float* out = g_bufA + (size_t)t * DIM;
    if (r >= H_ || c >= W_) {
        for (int ch = threadIdx.x; ch < DIM; ch += 128) out[ch] = b[ch];
        return;
    }
    const float* row = x + ((size_t)bb * HW + (size_t)r * W_ + c) * DIM;
    float v0 = row[threadIdx.x];
    float v1 = row[threadIdx.x + 128];
    float v2 = row[threadIdx.x + 256];
    float s = v0 + v1 + v2;
    float q = v0 * v0 + v1 * v1 + v2 * v2;
    blockReduce2_128(s, q);
    float mean = s * (1.f / DIM);
    float var = q * (1.f / DIM) - mean * mean;
    float rs = rsqrtf(var + LN_EPS);
    int ch = threadIdx.x;
    out[ch]       = (v0 - mean) * rs * g[ch]       + b[ch];
    out[ch + 128] = (v1 - mean) * rs * g[ch + 128] + b[ch + 128];
    out[ch + 256] = (v2 - mean) * rs * g[ch + 256] + b[ch + 256];
}

// ---------------- generic LN ----------------
__global__ void ln_kernel(const float* __restrict__ in,
                          const float* __restrict__ g,
                          const float* __restrict__ b,
                          float* __restrict__ out) {
    int t = blockIdx.x;
    const float* row = in + (size_t)t * DIM;
    float v0 = row[threadIdx.x];
    float v1 = row[threadIdx.x + 128];
    float v2 = row[threadIdx.x + 256];
    float s = v0 + v1 + v2;
    float q = v0 * v0 + v1 * v1 + v2 * v2;
    blockReduce2_128(s, q);
    float mean = s * (1.f / DIM);
    float var = q * (1.f / DIM) - mean * mean;
    float rs = rsqrtf(var + LN_EPS);
    float* o = out + (size_t)t * DIM;
    int ch = threadIdx.x;
    o[ch]       = (v0 - mean) * rs * g[ch]       + b[ch];
    o[ch + 128] = (v1 - mean) * rs * g[ch + 128] + b[ch + 128];
    o[ch + 256] = (v2 - mean) * rs * g[ch + 256] + b[ch + 256];
}

// ---------------- attention: one block per (window, head) ----------------
__global__ void attn_kernel(const float* __restrict__ attn_bias) {
    int w = blockIdx.x / NHEADS;
    int h = blockIdx.x % NHEADS;
    __shared__ float qs[NTOK][HDIM + 1];
    __shared__ float ks[NTOK][HDIM + 1];
    __shared__ float vs[NTOK][HDIM + 1];
    __shared__ float sc[NTOK][NTOK + 1];
    __shared__ float bsm[NTOK];
    int tid = threadIdx.x;

    for (int i = tid; i < NTOK * HDIM; i += 128) {
        int n = i / HDIM, d = i % HDIM;
        const float* base = g_bufB + ((size_t)w * NTOK + n) * (3 * DIM) + h * (3 * HDIM);
        qs[n][d] = base[d];
        ks[n][d] = base[HDIM + d];
        vs[n][d] = base[2 * HDIM + d];
    }
    if (tid < NTOK) bsm[tid] = attn_bias[h * NTOK + tid];
    __syncthreads();

    for (int i = tid; i < NTOK * NTOK; i += 128) {
        int n = i / NTOK, m = i % NTOK;
        float s = 0.f;
        #pragma unroll
        for (int d = 0; d < HDIM; d++) s += qs[n][d] * ks[m][d];
        int dr = abs(n / WSZ - m / WSZ);
        int dc = abs(n % WSZ - m % WSZ);
        sc[n][m] = s * ATTN_SCALE + bsm[dr * WSZ + dc];
    }
    __syncthreads();

    if (tid < NTOK) {
        float mx = -1e30f;
        #pragma unroll 7
        for (int m = 0; m < NTOK; m++) mx = fmaxf(mx, sc[tid][m]);
        float sum = 0.f;
        #pragma unroll 7
        for (int m = 0; m < NTOK; m++) {
            float e = expf(sc[tid][m] - mx);
            sc[tid][m] = e;
            sum += e;
        }
        float inv = 1.f / sum;
        #pragma unroll 7
        for (int m = 0; m < NTOK; m++) sc[tid][m] *= inv;
    }
    __syncthreads();

    for (int i = tid; i < NTOK * HDIM; i += 128) {
        int n = i / HDIM, d = i % HDIM;
        float s = 0.f;
        #pragma unroll 7
        for (int m = 0; m < NTOK; m++) s += sc[n][m] * vs[m][d];
        g_bufA[((size_t)w * NTOK + n) * DIM + h * HDIM + d] = s;
    }
}

// ---------------- depthwise 3x3 conv + BN (channel-last) ----------------
__global__ void conv_bn_kernel(const float* __restrict__ w9,
                               const float* __restrict__ bn_g,
                               const float* __restrict__ bn_b,
                               const float* __restrict__ bn_mean,
                               const float* __restrict__ bn_var) {
    int p = blockIdx.x;
    int bb = p >> 12;
    int pos = p & 4095;
    int r = pos >> 6, c = pos & 63;
    const float* base = g_bufB + (size_t)bb * HW * DIM;
    for (int ch = threadIdx.x; ch < DIM; ch += 128) {
        float s = 0.f;
        #pragma unroll
        for (int kh = 0; kh < 3; kh++) {
            int rr = r + kh - 1;
            if (rr < 0 || rr >= H_) continue;
            #pragma unroll
            for (int kw = 0; kw < 3; kw++) {
                int cc = c + kw - 1;
                if (cc < 0 || cc >= W_) continue;
                s += base[((size_t)rr * W_ + cc) * DIM + ch] * w9[ch * 9 + kh * 3 + kw];
            }
        }
        float o = (s - bn_mean[ch]) * rsqrtf(bn_var[ch] + LN_EPS) * bn_g[ch] + bn_b[ch];
        g_bufC[(size_t)p * DIM + ch] = o;
    }
}

// ---------------- launch ----------------
extern "C" void kernel_launch(void* const* d_in, const int* in_sizes, int n_in,
                              void* d_out, int out_size) {
    const float* x       = (const float*)d_in[0];
    const float* ln1_g   = (const float*)d_in[1];
    const float* ln1_b   = (const float*)d_in[2];
    const float* qkv_w   = (const float*)d_in[3];
    const float* qkv_b   = (const float*)d_in[4];
    const float* proj_w  = (const float*)d_in[5];
    const float* proj_b  = (const float*)d_in[6];
    const float* attn_b  = (const float*)d_in[7];
    const float* conv_w  = (const float*)d_in[8];
    const float* bn_g    = (const float*)d_in[9];
    const float* bn_b    = (const float*)d_in[10];
    const float* bn_mean = (const float*)d_in[11];
    const float* bn_var  = (const float*)d_in[12];
    const float* ln2_g   = (const float*)d_in[13];
    const float* ln2_b   = (const float*)d_in[14];
    const float* fc1_w   = (const float*)d_in[15];
    const float* fc1_b   = (const float*)d_in[16];
    const float* fc2_w   = (const float*)d_in[17];
    const float* fc2_b   = (const float*)d_in[18];
    float* out = (float*)d_out;

    float *pA, *pB, *pC, *pW;
    cudaGetSymbolAddress((void**)&pA, g_bufA);
    cudaGetSymbolAddress((void**)&pB, g_bufB);
    cudaGetSymbolAddress((void**)&pC, g_bufC);
    cudaGetSymbolAddress((void**)&pW, g_wt);

    // 0. weight transposes
    transpose_kernel<<<dim3(1152 / 32, 384 / 32), dim3(32, 8)>>>(qkv_w, pW + WT_QKV_OFF, 384, 1152);
    transpose_kernel<<<dim3(384 / 32, 384 / 32), dim3(32, 8)>>>(proj_w, pW + WT_PROJ_OFF, 384, 384);
    transpose_kernel<<<dim3(1536 / 32, 384 / 32), dim3(32, 8)>>>(fc1_w, pW + WT_FC1_OFF, 384, 1536);
    transpose_kernel<<<dim3(384 / 32, 1536 / 32), dim3(32, 8)>>>(fc2_w, pW + WT_FC2_OFF, 1536, 384);

    // 1. LN1 + window partition -> bufA
    ln1_win_kernel<<<TOK, 128>>>(x, ln1_g, ln1_b);

    // 2. QKV GEMM: (19600,384)@(384,1152) -> bufB
    mma_gemm<0><<<dim3(1152 / 128, (TOK + 127) / 128), 256>>>(
        pA, pW + WT_QKV_OFF, qkv_b, nullptr, pB, TOK, 1152, 384);

    // 3. attention -> bufA
    attn_kernel<<<NWIN * NHEADS, 128>>>(attn_b);

    // 4. proj GEMM + un-window + residual -> bufB (x1)
    mma_gemm<1><<<dim3(384 / 128, (TOK + 127) / 128), 256>>>(
        pA, pW + WT_PROJ_OFF, proj_b, x, pB, TOK, 384, 384);

    // 5. depthwise conv + BN -> bufC (x2)
    conv_bn_kernel<<<BATCH * HW, 128>>>(conv_w, bn_g, bn_b, bn_mean, bn_var);

    // 6. LN2: bufC -> bufA
    ln_kernel<<<BATCH * HW, 128>>>(pC, ln2_g, ln2_b, pA);

    // 7. FC1 + GELU: (16384,384)@(384,1536) -> bufB (h1)
    mma_gemm<2><<<dim3(1536 / 128, (BATCH * HW) / 128), 256>>>(
        pA, pW + WT_FC1_OFF, fc1_b, nullptr, pB, BATCH * HW, 1536, 384);

    // 8. FC2 + residual -> d_out: (16384,1536)@(1536,384)
    mma_gemm<3><<<dim3(384 / 128, (BATCH * HW) / 128), 256>>>(
        pB, pW + WT_FC2_OFF, fc2_b, pC, out, BATCH * HW, 384, 1536);
}

// round 8
// speedup vs baseline: 4.0031x; 1.6500x over previous
#include <cuda_runtime.h>
#include <cuda_fp16.h>
#include <math.h>
#include <stdint.h>

#define H_ 64
#define W_ 64
#define DIM 384
#define NHEADS 12
#define HDIM 32
#define WSZ 7
#define NTOK 49
#define NWIN 400
#define TOK 19600
#define BATCH 4
#define HW 4096
#define HID 1536
#define ATTN_SCALE 0.17677669529663689f
#define LN_EPS 1e-5f

// ---------------- scratch (device globals) ----------------
// g_hA (half): xn (19600x384) -> att (19600x384) -> ln2 (16384x384)
// g_hB (half): qkv (19600x1152) -> h1 (16384x1536)   [disjoint lifetimes]
// g_x1 (f32):  x + attn (residual stream, 16384x384)
// g_x2 (f32):  conv+BN out (16384x384)
__device__ __half g_hA[TOK * DIM];
__device__ __half g_hB[(size_t)BATCH * HW * HID > (size_t)TOK * 3 * DIM
                       ? (size_t)BATCH * HW * HID : (size_t)TOK * 3 * DIM];
__device__ float g_x1[BATCH * HW * DIM];
__device__ float g_x2[BATCH * HW * DIM];
// transposed half weights: qkv(1152x384) proj(384x384) fc1(1536x384) fc2(384x1536)
#define WT_QKV_OFF 0
#define WT_PROJ_OFF (1152*384)
#define WT_FC1_OFF  (WT_PROJ_OFF + 384*384)
#define WT_FC2_OFF  (WT_FC1_OFF + 1536*384)
__device__ __half g_hw[WT_FC2_OFF + 384*1536];

// ---------------- helpers ----------------
__device__ __forceinline__ uint32_t smem_u32(const void* p) {
    uint32_t a;
    asm("{ .reg .u64 t; cvta.to.shared.u64 t, %1; cvt.u32.u64 %0, t; }" : "=r"(a) : "l"(p));
    return a;
}
__device__ __forceinline__ void cp_async16(uint32_t dst, const void* src, int srcbytes) {
    asm volatile("cp.async.cg.shared.global [%0], [%1], 16, %2;"
                 :: "r"(dst), "l"(src), "r"(srcbytes));
}
#define CP_COMMIT() asm volatile("cp.async.commit_group;" ::: "memory")
#define CP_WAIT1()  asm volatile("cp.async.wait_group 1;" ::: "memory")
#define CP_WAIT0()  asm volatile("cp.async.wait_group 0;" ::: "memory")

__device__ __forceinline__ void mma_f16(float* c, const uint32_t* a, const uint32_t* b) {
    asm volatile(
        "mma.sync.aligned.m16n8k16.row.col.f32.f16.f16.f32 "
        "{%0,%1,%2,%3}, {%4,%5,%6,%7}, {%8,%9}, {%0,%1,%2,%3};"
        : "+f"(c[0]), "+f"(c[1]), "+f"(c[2]), "+f"(c[3])
        : "r"(a[0]), "r"(a[1]), "r"(a[2]), "r"(a[3]), "r"(b[0]), "r"(b[1]));
}

// ---------------- fp16 tensor-core GEMM via mma.sync ----------------
// C(M,N) = A(M,K) @ WT(N,K)^T + bias
// EPI 0: half store (qkv)           EPI 1: un-window + residual -> f32
// EPI 2: gelu -> half (h1)          EPI 3: v + res -> f32 (d_out)
#define BM 128
#define BN 128
#define BK 32
#define PADH 40   // halves per smem row (80B) -> conflict-free fragment LDS
template <int EPI>
__global__ __launch_bounds__(256)
void mma_gemm(const __half* __restrict__ A, const __half* __restrict__ WT,
              const float* __restrict__ bias, const float* __restrict__ res,
              float* __restrict__ C, int M, int N, int K) {
    __shared__ __half As[2][BM * PADH];
    __shared__ __half Bs[2][BN * PADH];
    int tid = threadIdx.x;
    int lane = tid & 31, wid = tid >> 5;
    int wm = wid & 1, wn = wid >> 1;        // warp grid 2 (M) x 4 (N)
    int row0 = blockIdx.y * BM, col0 = blockIdx.x * BN;
    int g4 = lane >> 2, t4 = lane & 3;

    float acc[4][4][4] = {};

    uint32_t sA[2] = { smem_u32(As[0]), smem_u32(As[1]) };
    uint32_t sB[2] = { smem_u32(Bs[0]), smem_u32(Bs[1]) };
    int nk = K / BK;

    // staging: 128 rows x 32 halves (64B = 4 x 16B chunks) per matrix
    #define STAGE(buf, k0) do { \
        int _k0 = (k0); \
        _Pragma("unroll") \
        for (int i = 0; i < 2; i++) { \
            int idx = tid + i * 256; \
            int r = idx >> 2, c = idx & 3; \
            int gr = row0 + r; \
            uint32_t d = sA[buf] + (uint32_t)(r * PADH + c * 8) * 2u; \
            cp_async16(d, A + (size_t)gr * K + _k0 + c * 8, gr < M ? 16 : 0); \
        } \
        _Pragma("unroll") \
        for (int i = 0; i < 2; i++) { \
            int idx = tid + i * 256; \
            int r = idx >> 2, c = idx & 3; \
            uint32_t d = sB[buf] + (uint32_t)(r * PADH + c * 8) * 2u; \
            cp_async16(d, WT + (size_t)(col0 + r) * K + _k0 + c * 8, 16); \
        } \
        CP_COMMIT(); \
    } while (0)

    STAGE(0, 0);
    for (int t = 0; t < nk; t++) {
        int buf = t & 1;
        if (t + 1 < nk) { STAGE(buf ^ 1, (t + 1) * BK); CP_WAIT1(); }
        else            { CP_WAIT0(); }
        __syncthreads();

        const __half* as = As[buf];
        const __half* bs = Bs[buf];
        #pragma unroll
        for (int kk = 0; kk < BK; kk += 16) {
            uint32_t af[4][4], bf[4][2];
            #pragma unroll
            for (int mi = 0; mi < 4; mi++) {
                int m = wm * 64 + mi * 16 + g4;
                af[mi][0] = *(const uint32_t*)(as + m * PADH + kk + 2 * t4);
                af[mi][1] = *(const uint32_t*)(as + (m + 8) * PADH + kk + 2 * t4);
                af[mi][2] = *(const uint32_t*)(as + m * PADH + kk + 2 * t4 + 8);
                af[mi][3] = *(const uint32_t*)(as + (m + 8) * PADH + kk + 2 * t4 + 8);
            }
            #pragma unroll
            for (int nj = 0; nj < 4; nj++) {
                int n = wn * 32 + nj * 8 + g4;
                bf[nj][0] = *(const uint32_t*)(bs + n * PADH + kk + 2 * t4);
                bf[nj][1] = *(const uint32_t*)(bs + n * PADH + kk + 2 * t4 + 8);
            }
            #pragma unroll
            for (int mi = 0; mi < 4; mi++)
                #pragma unroll
                for (int nj = 0; nj < 4; nj++)
                    mma_f16(acc[mi][nj], af[mi], bf[nj]);
        }
        __syncthreads();
    }

    // ---------------- epilogue ----------------
    __half* Ch = (__half*)C;
    #pragma unroll
    for (int mi = 0; mi < 4; mi++) {
        #pragma unroll
        for (int half_ = 0; half_ < 2; half_++) {
            int r = row0 + wm * 64 + mi * 16 + g4 + half_ * 8;
            if (r >= M) continue;
            size_t obase = 0;
            bool valid = true;
            if (EPI == 1) {
                int w = r / NTOK, n = r % NTOK;
                int bb = w / 100, wh = (w / 10) % 10, ww = w % 10;
                int rr = wh * WSZ + n / WSZ;
                int cc = ww * WSZ + n % WSZ;
                valid = (rr < H_) && (cc < W_);
                if (valid) obase = ((size_t)bb * HW + (size_t)rr * W_ + cc) * DIM;
            }
            #pragma unroll
            for (int nj = 0; nj < 4; nj++) {
                int cn = col0 + wn * 32 + nj * 8 + 2 * t4;
                float v0 = acc[mi][nj][half_ * 2 + 0] + bias[cn];
                float v1 = acc[mi][nj][half_ * 2 + 1] + bias[cn + 1];
                if (EPI == 0) {
                    *(__half2*)(Ch + (size_t)r * N + cn) = __floats2half2_rn(v0, v1);
                } else if (EPI == 1) {
                    if (valid) {
                        float2 rr2 = *(const float2*)(res + obase + cn);
                        *(float2*)(C + obase + cn) = make_float2(v0 + rr2.x, v1 + rr2.y);
                    }
                } else if (EPI == 2) {
                    v0 = 0.5f * v0 * (1.f + erff(v0 * 0.70710678118654752f));
                    v1 = 0.5f * v1 * (1.f + erff(v1 * 0.70710678118654752f));
                    *(__half2*)(Ch + (size_t)r * N + cn) = __floats2half2_rn(v0, v1);
                } else {
                    float2 rr2 = *(const float2*)(res + (size_t)r * N + cn);
                    *(float2*)(C + (size_t)r * N + cn) = make_float2(v0 + rr2.x, v1 + rr2.y);
                }
            }
        }
    }
}

// ---------------- weight transpose+convert: WT(N,K) half <- W(K,N) f32 -------
__global__ void transpose_kernel(const float* __restrict__ W, __half* __restrict__ WT,
                                 int K, int N) {
    __shared__ float t[32][33];
    int n0 = blockIdx.x * 32, k0 = blockIdx.y * 32;
    int tx = threadIdx.x, ty = threadIdx.y;
    #pragma unroll
    for (int i = 0; i < 32; i += 8)
        t[ty + i][tx] = W[(size_t)(k0 + ty + i) * N + n0 + tx];
    __syncthreads();
    #pragma unroll
    for (int i = 0; i < 32; i += 8)
        WT[(size_t)(n0 + ty + i) * K + k0 + tx] = __float2half(t[tx][ty + i]);
}

// ---------------- block reduce (128 threads) ----------------
__device__ __forceinline__ void blockReduce2_128(float& s, float& q) {
    __shared__ float sh[8];
    int lane = threadIdx.x & 31, warp = threadIdx.x >> 5;
    #pragma unroll
    for (int o = 16; o > 0; o >>= 1) {
        s += __shfl_down_sync(0xffffffffu, s, o);
        q += __shfl_down_sync(0xffffffffu, q, o);
    }
    if (lane == 0) { sh[warp] = s; sh[4 + warp] = q; }
    __syncthreads();
    if (threadIdx.x == 0) {
        float a = 0.f, b = 0.f;
        #pragma unroll
        for (int i = 0; i < 4; i++) { a += sh[i]; b += sh[4 + i]; }
        sh[0] = a; sh[4] = b;
    }
    __syncthreads();
    s = sh[0]; q = sh[4];
    __syncthreads();
}

// ---------------- LN1 + window gather -> half ----------------
__global__ void ln1_win_kernel(const float* __restrict__ x,
                               const float* __restrict__ g,
                               const float* __restrict__ b) {
    int t = blockIdx.x;
    int w = t / NTOK, n = t % NTOK;
    int bb = w / 100, wh = (w / 10) % 10, ww = w % 10;
    int r = wh * WSZ + n / WSZ;
    int c = ww * WSZ + n % WSZ;
    __half* out = g_hA + (size_t)t * DIM;
    if (r >= H_ || c >= W_) {
        for (int ch = threadIdx.x; ch < DIM; ch += 128) out[ch] = __float2half(b[ch]);
        return;
    }
    const float* row = x + ((size_t)bb * HW + (size_t)r * W_ + c) * DIM;
    float v0 = row[threadIdx.x];
    float v1 = row[threadIdx.x + 128];
    float v2 = row[threadIdx.x + 256];
    float s = v0 + v1 + v2;
    float q = v0 * v0 + v1 * v1 + v2 * v2;
    blockReduce2_128(s, q);
    float mean = s * (1.f / DIM);
    float var = q * (1.f / DIM) - mean * mean;
    float rs = rsqrtf(var + LN_EPS);
    int ch = threadIdx.x;
    out[ch]       = __float2half((v0 - mean) * rs * g[ch]       + b[ch]);
    out[ch + 128] = __float2half((v1 - mean) * rs * g[ch + 128] + b[ch + 128]);
    out[ch + 256] = __float2half((v2 - mean) * rs * g[ch + 256] + b[ch + 256]);
}

// ---------------- LN2 -> half ----------------
__global__ void ln_kernel(const float* __restrict__ in,
                          const float* __restrict__ g,
                          const float* __restrict__ b,
                          __half* __restrict__ out) {
    int t = blockIdx.x;
    const float* row = in + (size_t)t * DIM;
    float v0 = row[threadIdx.x];
    float v1 = row[threadIdx.x + 128];
    float v2 = row[threadIdx.x + 256];
    float s = v0 + v1 + v2;
    float q = v0 * v0 + v1 * v1 + v2 * v2;
    blockReduce2_128(s, q);
    float mean = s * (1.f / DIM);
    float var = q * (1.f / DIM) - mean * mean;
    float rs = rsqrtf(var + LN_EPS);
    __half* o = out + (size_t)t * DIM;
    int ch = threadIdx.x;
    o[ch]       = __float2half((v0 - mean) * rs * g[ch]       + b[ch]);
    o[ch + 128] = __float2half((v1 - mean) * rs * g[ch + 128] + b[ch + 128]);
    o[ch + 256] = __float2half((v2 - mean) * rs * g[ch + 256] + b[ch + 256]);
}

// ---------------- attention: block per (window, head), register-tiled -------
__global__ void attn_kernel(const float* __restrict__ attn_bias) {
    int w = blockIdx.x / NHEADS;
    int h = blockIdx.x % NHEADS;
    __shared__ float qs[52 * 33], ks[52 * 33], vs[52 * 33];
    __shared__ float sc[52 * 52];
    __shared__ float bsm[NTOK];
    int tid = threadIdx.x;

    // zero pad rows 49..51
    for (int i = tid; i < 3 * 33; i += 128) {
        qs[49 * 33 + i] = 0.f; ks[49 * 33 + i] = 0.f; vs[49 * 33 + i] = 0.f;
    }
    const __half* qkv = g_hB;
    for (int i = tid; i < NTOK * HDIM; i += 128) {
        int n = i >> 5, d = i & 31;
        const __half* base = qkv + ((size_t)w * NTOK + n) * (3 * DIM) + h * (3 * HDIM);
        qs[n * 33 + d] = __half2float(base[d]);
        ks[n * 33 + d] = __half2float(base[HDIM + d]);
        vs[n * 33 + d] = __half2float(base[2 * HDIM + d]);
    }
    if (tid < NTOK) bsm[tid] = attn_bias[h * NTOK + tid];
    __syncthreads();

    // scores: 13x13 grid of 4x4 tiles
    for (int tile = tid; tile < 169; tile += 128) {
        int n0 = (tile / 13) * 4, m0 = (tile % 13) * 4;
        float acc[4][4] = {};
        for (int d = 0; d < HDIM; d++) {
            float qv[4], kv[4];
            #pragma unroll
            for (int i = 0; i < 4; i++) qv[i] = qs[(n0 + i) * 33 + d];
            #pragma unroll
            for (int j = 0; j < 4; j++) kv[j] = ks[(m0 + j) * 33 + d];
            #pragma unroll
            for (int i = 0; i < 4; i++)
                #pragma unroll
                for (int j = 0; j < 4; j++)
                    acc[i][j] += qv[i] * kv[j];
        }
        #pragma unroll
        for (int i = 0; i < 4; i++) {
            int n = n0 + i;
            if (n >= NTOK) break;
            #pragma unroll
            for (int j = 0; j < 4; j++) {
                int m = m0 + j;
                if (m >= NTOK) continue;
                int dr = abs(n / WSZ - m / WSZ);
                int dc = abs(n % WSZ - m % WSZ);
                sc[n * 52 + m] = acc[i][j] * ATTN_SCALE + bsm[dr * WSZ + dc];
            }
        }
    }
    __syncthreads();

    // softmax rows (+ zero pad rows 49..51)
    if (tid < 52) {
        if (tid < NTOK) {
            float mx = -1e30f;
            #pragma unroll 7
            for (int m = 0; m < NTOK; m++) mx = fmaxf(mx, sc[tid * 52 + m]);
            float sum = 0.f;
            #pragma unroll 7
            for (int m = 0; m < NTOK; m++) {
                float e = expf(sc[tid * 52 + m] - mx);
                sc[tid * 52 + m] = e;
                sum += e;
            }
            float inv = 1.f / sum;
            #pragma unroll 7
            for (int m = 0; m < NTOK; m++) sc[tid * 52 + m] *= inv;
        } else {
            for (int m = 0; m < NTOK; m++) sc[tid * 52 + m] = 0.f;
        }
    }
    __syncthreads();

    // AV: 13 n-tiles x 8 d-tiles of 4x4
    for (int tile = tid; tile < 104; tile += 128) {
        int n0 = (tile / 8) * 4, d0 = (tile % 8) * 4;
        float acc[4][4] = {};
        for (int m = 0; m < NTOK; m++) {
            float sv[4], vv[4];
            #pragma unroll
            for (int i = 0; i < 4; i++) sv[i] = sc[(n0 + i) * 52 + m];
            #pragma unroll
            for (int j = 0; j < 4; j++) vv[j] = vs[m * 33 + d0 + j];
            #pragma unroll
            for (int i = 0; i < 4; i++)
                #pragma unroll
                for (int j = 0; j < 4; j++)
                    acc[i][j] += sv[i] * vv[j];
        }
        #pragma unroll
        for (int i = 0; i < 4; i++) {
            int n = n0 + i;
            if (n >= NTOK) break;
            __half* o = g_hA + ((size_t)w * NTOK + n) * DIM + h * HDIM + d0;
            #pragma unroll
            for (int j = 0; j < 4; j++) o[j] = __float2half(acc[i][j]);
        }
    }
}

// ---------------- depthwise 3x3 conv + BN (channel-last) ----------------
__global__ void conv_bn_kernel(const float* __restrict__ w9,
                               const float* __restrict__ bn_g,
                               const float* __restrict__ bn_b,
                               const float* __restrict__ bn_mean,
                               const float* __restrict__ bn_var) {
    int p = blockIdx.x;
    int bb = p >> 12;
    int pos = p & 4095;
    int r = pos >> 6, c = pos & 63;
    const float* base = g_x1 + (size_t)bb * HW * DIM;
    for (int ch = threadIdx.x; ch < DIM; ch += 128) {
        float s = 0.f;
        #pragma unroll
        for (int kh = 0; kh < 3; kh++) {
            int rr = r + kh - 1;
            if (rr < 0 || rr >= H_) continue;
            #pragma unroll
            for (int kw = 0; kw < 3; kw++) {
                int cc = c + kw - 1;
                if (cc < 0 || cc >= W_) continue;
                s += base[((size_t)rr * W_ + cc) * DIM + ch] * w9[ch * 9 + kh * 3 + kw];
            }
        }
        float o = (s - bn_mean[ch]) * rsqrtf(bn_var[ch] + LN_EPS) * bn_g[ch] + bn_b[ch];
        g_x2[(size_t)p * DIM + ch] = o;
    }
}

// ---------------- launch ----------------
extern "C" void kernel_launch(void* const* d_in, const int* in_sizes, int n_in,
                              void* d_out, int out_size) {
    const float* x       = (const float*)d_in[0];
    const float* ln1_g   = (const float*)d_in[1];
    const float* ln1_b   = (const float*)d_in[2];
    const float* qkv_w   = (const float*)d_in[3];
    const float* qkv_b   = (const float*)d_in[4];
    const float* proj_w  = (const float*)d_in[5];
    const float* proj_b  = (const float*)d_in[6];
    const float* attn_b  = (const float*)d_in[7];
    const float* conv_w  = (const float*)d_in[8];
    const float* bn_g    = (const float*)d_in[9];
    const float* bn_b    = (const float*)d_in[10];
    const float* bn_mean = (const float*)d_in[11];
    const float* bn_var  = (const float*)d_in[12];
    const float* ln2_g   = (const float*)d_in[13];
    const float* ln2_b   = (const float*)d_in[14];
    const float* fc1_w   = (const float*)d_in[15];
    const float* fc1_b   = (const float*)d_in[16];
    const float* fc2_w   = (const float*)d_in[17];
    const float* fc2_b   = (const float*)d_in[18];
    float* out = (float*)d_out;

    __half *phA, *phB, *phW;
    float *px1, *px2;
    cudaGetSymbolAddress((void**)&phA, g_hA);
    cudaGetSymbolAddress((void**)&phB, g_hB);
    cudaGetSymbolAddress((void**)&phW, g_hw);
    cudaGetSymbolAddress((void**)&px1, g_x1);
    cudaGetSymbolAddress((void**)&px2, g_x2);

    // 0. weight transposes (f32 -> half, (N,K) layout)
    transpose_kernel<<<dim3(1152 / 32, 384 / 32), dim3(32, 8)>>>(qkv_w, phW + WT_QKV_OFF, 384, 1152);
    transpose_kernel<<<dim3(384 / 32, 384 / 32), dim3(32, 8)>>>(proj_w, phW + WT_PROJ_OFF, 384, 384);
    transpose_kernel<<<dim3(1536 / 32, 384 / 32), dim3(32, 8)>>>(fc1_w, phW + WT_FC1_OFF, 384, 1536);
    transpose_kernel<<<dim3(384 / 32, 1536 / 32), dim3(32, 8)>>>(fc2_w, phW + WT_FC2_OFF, 1536, 384);

    // 1. LN1 + window partition -> hA (half)
    ln1_win_kernel<<<TOK, 128>>>(x, ln1_g, ln1_b);

    // 2. QKV GEMM -> hB (half)
    mma_gemm<0><<<dim3(1152 / 128, (TOK + 127) / 128), 256>>>(
        phA, phW + WT_QKV_OFF, qkv_b, nullptr, (float*)phB, TOK, 1152, 384);

    // 3. attention -> hA (half)
    attn_kernel<<<NWIN * NHEADS, 128>>>(attn_b);

    // 4. proj GEMM + un-window + residual -> x1 (f32)
    mma_gemm<1><<<dim3(384 / 128, (TOK + 127) / 128), 256>>>(
        phA, phW + WT_PROJ_OFF, proj_b, x, px1, TOK, 384, 384);

    // 5. depthwise conv + BN -> x2 (f32)
    conv_bn_kernel<<<BATCH * HW, 128>>>(conv_w, bn_g, bn_b, bn_mean, bn_var);

    // 6. LN2: x2 -> hA (half)
    ln_kernel<<<BATCH * HW, 128>>>(px2, ln2_g, ln2_b, phA);

    // 7. FC1 + GELU -> hB (half h1)
    mma_gemm<2><<<dim3(1536 / 128, (BATCH * HW) / 128), 256>>>(
        phA, phW + WT_FC1_OFF, fc1_b, nullptr, (float*)phB, BATCH * HW, 1536, 384);

    // 8. FC2 + residual -> d_out (f32)
    mma_gemm<3><<<dim3(384 / 128, (BATCH * HW) / 128), 256>>>(
        phB, phW + WT_FC2_OFF, fc2_b, px2, out, BATCH * HW, 384, 1536);
}

// round 10
// speedup vs baseline: 4.7578x; 1.1885x over previous
#include <cuda_runtime.h>
#include <cuda_fp16.h>
#include <math.h>
#include <stdint.h>

#define H_ 64
#define W_ 64
#define DIM 384
#define NHEADS 12
#define HDIM 32
#define WSZ 7
#define NTOK 49
#define NWIN 400
#define TOK 19600
#define BATCH 4
#define HW 4096
#define HID 1536
#define ATTN_SCALE 0.17677669529663689f
#define LN_EPS 1e-5f

// ---------------- scratch (device globals) ----------------
__device__ __half g_hA[TOK * DIM];
__device__ __half g_hB[(size_t)BATCH * HW * HID > (size_t)TOK * 3 * DIM
                       ? (size_t)BATCH * HW * HID : (size_t)TOK * 3 * DIM];
__device__ float g_x1[BATCH * HW * DIM];
__device__ float g_x2[BATCH * HW * DIM];
#define WT_QKV_OFF 0
#define WT_PROJ_OFF (1152*384)
#define WT_FC1_OFF  (WT_PROJ_OFF + 384*384)
#define WT_FC2_OFF  (WT_FC1_OFF + 1536*384)
__device__ __half g_hw[WT_FC2_OFF + 384*1536];

// ---------------- helpers ----------------
__device__ __forceinline__ uint32_t smem_u32(const void* p) {
    uint32_t a;
    asm("{ .reg .u64 t; cvta.to.shared.u64 t, %1; cvt.u32.u64 %0, t; }" : "=r"(a) : "l"(p));
    return a;
}
__device__ __forceinline__ void cp_async16(uint32_t dst, const void* src, int srcbytes) {
    asm volatile("cp.async.cg.shared.global [%0], [%1], 16, %2;"
                 :: "r"(dst), "l"(src), "r"(srcbytes));
}
#define CP_COMMIT() asm volatile("cp.async.commit_group;" ::: "memory")
#define CP_WAIT1()  asm volatile("cp.async.wait_group 1;" ::: "memory")
#define CP_WAIT0()  asm volatile("cp.async.wait_group 0;" ::: "memory")

__device__ __forceinline__ void mma_f16(float* c, const uint32_t* a, const uint32_t* b) {
    asm volatile(
        "mma.sync.aligned.m16n8k16.row.col.f32.f16.f16.f32 "
        "{%0,%1,%2,%3}, {%4,%5,%6,%7}, {%8,%9}, {%0,%1,%2,%3};"
        : "+f"(c[0]), "+f"(c[1]), "+f"(c[2]), "+f"(c[3])
        : "r"(a[0]), "r"(a[1]), "r"(a[2]), "r"(a[3]), "r"(b[0]), "r"(b[1]));
}
__device__ __forceinline__ uint32_t packh2(float x, float y) {
    __half2 h = __floats2half2_rn(x, y);
    return *(uint32_t*)&h;
}

// ---------------- fp16 tensor-core GEMM ----------------
#define BM 128
#define BN 128
#define BK 32
#define PADH 40
template <int EPI>
__global__ __launch_bounds__(256)
void mma_gemm(const __half* __restrict__ A, const __half* __restrict__ WT,
              const float* __restrict__ bias, const float* __restrict__ res,
              float* __restrict__ C, int M, int N, int K) {
    __shared__ __half As[2][BM * PADH];
    __shared__ __half Bs[2][BN * PADH];
    int tid = threadIdx.x;
    int lane = tid & 31, wid = tid >> 5;
    int wm = wid & 1, wn = wid >> 1;
    int row0 = blockIdx.y * BM, col0 = blockIdx.x * BN;
    int g4 = lane >> 2, t4 = lane & 3;

    float acc[4][4][4] = {};
    uint32_t sA[2] = { smem_u32(As[0]), smem_u32(As[1]) };
    uint32_t sB[2] = { smem_u32(Bs[0]), smem_u32(Bs[1]) };
    int nk = K / BK;

    #define STAGE(buf, k0) do { \
        int _k0 = (k0); \
        _Pragma("unroll") \
        for (int i = 0; i < 2; i++) { \
            int idx = tid + i * 256; \
            int r = idx >> 2, c = idx & 3; \
            int gr = row0 + r; \
            uint32_t d = sA[buf] + (uint32_t)(r * PADH + c * 8) * 2u; \
            cp_async16(d, A + (size_t)gr * K + _k0 + c * 8, gr < M ? 16 : 0); \
        } \
        _Pragma("unroll") \
        for (int i = 0; i < 2; i++) { \
            int idx = tid + i * 256; \
            int r = idx >> 2, c = idx & 3; \
            uint32_t d = sB[buf] + (uint32_t)(r * PADH + c * 8) * 2u; \
            cp_async16(d, WT + (size_t)(col0 + r) * K + _k0 + c * 8, 16); \
        } \
        CP_COMMIT(); \
    } while (0)

    STAGE(0, 0);
    for (int t = 0; t < nk; t++) {
        int buf = t & 1;
        if (t + 1 < nk) { STAGE(buf ^ 1, (t + 1) * BK); CP_WAIT1(); }
        else            { CP_WAIT0(); }
        __syncthreads();

        const __half* as = As[buf];
        const __half* bs = Bs[buf];
        #pragma unroll
        for (int kk = 0; kk < BK; kk += 16) {
            uint32_t af[4][4], bf[4][2];
            #pragma unroll
            for (int mi = 0; mi < 4; mi++) {
                int m = wm * 64 + mi * 16 + g4;
                af[mi][0] = *(const uint32_t*)(as + m * PADH + kk + 2 * t4);
                af[mi][1] = *(const uint32_t*)(as + (m + 8) * PADH + kk + 2 * t4);
                af[mi][2] = *(const uint32_t*)(as + m * PADH + kk + 2 * t4 + 8);
                af[mi][3] = *(const uint32_t*)(as + (m + 8) * PADH + kk + 2 * t4 + 8);
            }
            #pragma unroll
            for (int nj = 0; nj < 4; nj++) {
                int n = wn * 32 + nj * 8 + g4;
                bf[nj][0] = *(const uint32_t*)(bs + n * PADH + kk + 2 * t4);
                bf[nj][1] = *(const uint32_t*)(bs + n * PADH + kk + 2 * t4 + 8);
            }
            #pragma unroll
            for (int mi = 0; mi < 4; mi++)
                #pragma unroll
                for (int nj = 0; nj < 4; nj++)
                    mma_f16(acc[mi][nj], af[mi], bf[nj]);
        }
        __syncthreads();
    }

    __half* Ch = (__half*)C;
    #pragma unroll
    for (int mi = 0; mi < 4; mi++) {
        #pragma unroll
        for (int half_ = 0; half_ < 2; half_++) {
            int r = row0 + wm * 64 + mi * 16 + g4 + half_ * 8;
            if (r >= M) continue;
            size_t obase = 0;
            bool valid = true;
            if (EPI == 1) {
                int w = r / NTOK, n = r % NTOK;
                int bb = w / 100, wh = (w / 10) % 10, ww = w % 10;
                int rr = wh * WSZ + n / WSZ;
                int cc = ww * WSZ + n % WSZ;
                valid = (rr < H_) && (cc < W_);
                if (valid) obase = ((size_t)bb * HW + (size_t)rr * W_ + cc) * DIM;
            }
            #pragma unroll
            for (int nj = 0; nj < 4; nj++) {
                int cn = col0 + wn * 32 + nj * 8 + 2 * t4;
                float v0 = acc[mi][nj][half_ * 2 + 0] + bias[cn];
                float v1 = acc[mi][nj][half_ * 2 + 1] + bias[cn + 1];
                if (EPI == 0) {
                    *(__half2*)(Ch + (size_t)r * N + cn) = __floats2half2_rn(v0, v1);
                } else if (EPI == 1) {
                    if (valid) {
                        float2 rr2 = *(const float2*)(res + obase + cn);
                        *(float2*)(C + obase + cn) = make_float2(v0 + rr2.x, v1 + rr2.y);
                    }
                } else if (EPI == 2) {
                    v0 = 0.5f * v0 * (1.f + erff(v0 * 0.70710678118654752f));
                    v1 = 0.5f * v1 * (1.f + erff(v1 * 0.70710678118654752f));
                    *(__half2*)(Ch + (size_t)r * N + cn) = __floats2half2_rn(v0, v1);
                } else {
                    float2 rr2 = *(const float2*)(res + (size_t)r * N + cn);
                    *(float2*)(C + (size_t)r * N + cn) = make_float2(v0 + rr2.x, v1 + rr2.y);
                }
            }
        }
    }
}

// ---------------- merged weight transpose: all 4 matrices, one launch -------
__global__ void transpose_all(const float* __restrict__ qkv_w,
                              const float* __restrict__ proj_w,
                              const float* __restrict__ fc1_w,
                              const float* __restrict__ fc2_w,
                              __half* __restrict__ wt) {
    __shared__ float t[32][33];
    int b = blockIdx.x;
    const float* W; __half* WT; int K, N, tt;
    if (b < 432)       { W = qkv_w;  WT = wt + WT_QKV_OFF;  K = 384;  N = 1152; tt = b; }
    else if (b < 576)  { W = proj_w; WT = wt + WT_PROJ_OFF; K = 384;  N = 384;  tt = b - 432; }
    else if (b < 1152) { W = fc1_w;  WT = wt + WT_FC1_OFF;  K = 384;  N = 1536; tt = b - 576; }
    else               { W = fc2_w;  WT = wt + WT_FC2_OFF;  K = 1536; N = 384;  tt = b - 1152; }
    int nx = N / 32;
    int n0 = (tt % nx) * 32, k0 = (tt / nx) * 32;
    int tx = threadIdx.x, ty = threadIdx.y;
    #pragma unroll
    for (int i = 0; i < 32; i += 8)
        t[ty + i][tx] = W[(size_t)(k0 + ty + i) * N + n0 + tx];
    __syncthreads();
    #pragma unroll
    for (int i = 0; i < 32; i += 8)
        WT[(size_t)(n0 + ty + i) * K + k0 + tx] = __float2half(t[tx][ty + i]);
}

// ---------------- block reduce (128 threads) ----------------
__device__ __forceinline__ void blockReduce2_128(float& s, float& q) {
    __shared__ float sh[8];
    int lane = threadIdx.x & 31, warp = threadIdx.x >> 5;
    #pragma unroll
    for (int o = 16; o > 0; o >>= 1) {
        s += __shfl_down_sync(0xffffffffu, s, o);
        q += __shfl_down_sync(0xffffffffu, q, o);
    }
    if (lane == 0) { sh[warp] = s; sh[4 + warp] = q; }
    __syncthreads();
    if (threadIdx.x == 0) {
        float a = 0.f, b = 0.f;
        #pragma unroll
        for (int i = 0; i < 4; i++) { a += sh[i]; b += sh[4 + i]; }
        sh[0] = a; sh[4] = b;
    }
    __syncthreads();
    s = sh[0]; q = sh[4];
    __syncthreads();
}

// ---------------- LN1 + window gather -> half ----------------
__global__ void ln1_win_kernel(const float* __restrict__ x,
                               const float* __restrict__ g,
                               const float* __restrict__ b) {
    int t = blockIdx.x;
    int w = t / NTOK, n = t % NTOK;
    int bb = w / 100, wh = (w / 10) % 10, ww = w % 10;
    int r = wh * WSZ + n / WSZ;
    int c = ww * WSZ + n % WSZ;
    __half* out = g_hA + (size_t)t * DIM;
    if (r >= H_ || c >= W_) {
        for (int ch = threadIdx.x; ch < DIM; ch += 128) out[ch] = __float2half(b[ch]);
        return;
    }
    const float* row = x + ((size_t)bb * HW + (size_t)r * W_ + c) * DIM;
    float v0 = row[threadIdx.x];
    float v1 = row[threadIdx.x + 128];
    float v2 = row[threadIdx.x + 256];
    float s = v0 + v1 + v2;
    float q = v0 * v0 + v1 * v1 + v2 * v2;
    blockReduce2_128(s, q);
    float mean = s * (1.f / DIM);
    float var = q * (1.f / DIM) - mean * mean;
    float rs = rsqrtf(var + LN_EPS);
    int ch = threadIdx.x;
    out[ch]       = __float2half((v0 - mean) * rs * g[ch]       + b[ch]);
    out[ch + 128] = __float2half((v1 - mean) * rs * g[ch + 128] + b[ch + 128]);
    out[ch + 256] = __float2half((v2 - mean) * rs * g[ch + 256] + b[ch + 256]);
}

// ---------------- attention via mma.sync: warp-pair per (window, head) ------
// per unit (2 warps): S = Q@K^T (64x64 padded), fragment softmax, O = P@V.
#define AUNITS 4
#define UNIT_HALVES 7424   // Qs 64x40 + Ks 64x40 + Vt 32x72
__global__ __launch_bounds__(256)
void attn_mma(const float* __restrict__ attn_bias) {
    extern __shared__ __half smh[];
    __shared__ unsigned char d7[64], m7[64];
    int tid = threadIdx.x;
    int unit = tid >> 6;
    int u_tid = tid & 63;
    int lane = tid & 31;
    int wh = (tid >> 5) & 1;          // warp half: rows wh*32..wh*32+31
    int g4 = lane >> 2, t4 = lane & 3;
    int gidx = blockIdx.x * AUNITS + unit;
    int w = gidx / NHEADS, h = gidx % NHEADS;

    __half* Qs = smh + unit * UNIT_HALVES;
    __half* Ks = Qs + 2560;
    __half* Vt = Ks + 2560;           // 32 rows (d) x 72 halves (m + pad)
    float* bsm = (float*)(smh + 4 * UNIT_HALVES) + unit * 49;

    if (tid < 64) { d7[tid] = (unsigned char)(tid / 7); m7[tid] = (unsigned char)(tid % 7); }

    // zero unit region (covers pad rows/cols)
    uint32_t* uz = (uint32_t*)Qs;
    for (int i = u_tid; i < UNIT_HALVES / 2; i += 64) uz[i] = 0u;
    __syncthreads();

    // fill Q, K (row n, 32 halves) and V transposed (row d, col m)
    const uint32_t* qkvw = (const uint32_t*)g_hB;
    for (int i = u_tid; i < NTOK * 16; i += 64) {
        int n = i >> 4, d2 = i & 15;
        size_t base = ((size_t)(w * NTOK + n) * 1152 + h * 96) >> 1;
        uint32_t qw = qkvw[base + d2];
        uint32_t kw = qkvw[base + 16 + d2];
        uint32_t vw = qkvw[base + 32 + d2];
        ((uint32_t*)Qs)[n * 20 + d2] = qw;
        ((uint32_t*)Ks)[n * 20 + d2] = kw;
        __half2 vv = *(__half2*)&vw;
        Vt[(2 * d2) * 72 + n] = __low2half(vv);
        Vt[(2 * d2 + 1) * 72 + n] = __high2half(vv);
    }
    if (u_tid < NTOK) bsm[u_tid] = attn_bias[h * NTOK + u_tid];
    __syncthreads();

    // ---- scores: 2 mi-tiles x 8 nj-tiles, K=32 (2 k16 steps) ----
    const uint32_t* Qw = (const uint32_t*)Qs;
    const uint32_t* Kw = (const uint32_t*)Ks;
    float s[2][8][4] = {};
    #pragma unroll
    for (int kk = 0; kk < 2; kk++) {
        uint32_t a[2][4], b[8][2];
        #pragma unroll
        for (int mi = 0; mi < 2; mi++) {
            int r = wh * 32 + mi * 16 + g4;
            a[mi][0] = Qw[r * 20 + kk * 8 + t4];
            a[mi][1] = Qw[(r + 8) * 20 + kk * 8 + t4];
            a[mi][2] = Qw[r * 20 + kk * 8 + t4 + 4];
            a[mi][3] = Qw[(r + 8) * 20 + kk * 8 + t4 + 4];
        }
        #pragma unroll
        for (int nj = 0; nj < 8; nj++) {
            int n = nj * 8 + g4;
            b[nj][0] = Kw[n * 20 + kk * 8 + t4];
            b[nj][1] = Kw[n * 20 + kk * 8 + t4 + 4];
        }
        #pragma unroll
        for (int mi = 0; mi < 2; mi++)
            #pragma unroll
            for (int nj = 0; nj < 8; nj++)
                mma_f16(s[mi][nj], a[mi], b[nj]);
    }

    // ---- bias + mask + softmax in fragments ----
    #pragma unroll
    for (int mi = 0; mi < 2; mi++) {
        #pragma unroll
        for (int hf = 0; hf < 2; hf++) {
            int row = wh * 32 + mi * 16 + hf * 8 + g4;
            bool rowok = row < NTOK;
            int rd = d7[row], rm = m7[row];
            float mx = -1e30f;
            #pragma unroll
            for (int nj = 0; nj < 8; nj++) {
                #pragma unroll
                for (int e = 0; e < 2; e++) {
                    int col = nj * 8 + 2 * t4 + e;
                    float v = s[mi][nj][hf * 2 + e] * ATTN_SCALE;
                    if (rowok && col < NTOK) {
                        int dr = abs(rd - (int)d7[col]);
                        int dc = abs(rm - (int)m7[col]);
                        v += bsm[dr * 7 + dc];
                    } else v = -1e30f;
                    s[mi][nj][hf * 2 + e] = v;
                    mx = fmaxf(mx, v);
                }
            }
            mx = fmaxf(mx, __shfl_xor_sync(0xffffffffu, mx, 1));
            mx = fmaxf(mx, __shfl_xor_sync(0xffffffffu, mx, 2));
            if (mx < -1e29f) mx = 0.f;
            float sum = 0.f;
            #pragma unroll
            for (int nj = 0; nj < 8; nj++) {
                #pragma unroll
                for (int e = 0; e < 2; e++) {
                    float ev = __expf(s[mi][nj][hf * 2 + e] - mx);
                    s[mi][nj][hf * 2 + e] = ev;
                    sum += ev;
                }
            }
            sum += __shfl_xor_sync(0xffffffffu, sum, 1);
            sum += __shfl_xor_sync(0xffffffffu, sum, 2);
            float inv = rowok ? 1.f / sum : 0.f;
            #pragma unroll
            for (int nj = 0; nj < 8; nj++) {
                s[mi][nj][hf * 2 + 0] *= inv;
                s[mi][nj][hf * 2 + 1] *= inv;
            }
        }
    }

    // ---- O = P @ V : K=64 (4 k16 steps), N=32 (4 n8 tiles) ----
    float o[2][4][4] = {};
    const uint32_t* Vw = (const uint32_t*)Vt;
    #pragma unroll
    for (int kkA = 0; kkA < 4; kkA++) {
        uint32_t b[4][2];
        #pragma unroll
        for (int njd = 0; njd < 4; njd++) {
            int d = njd * 8 + g4;
            b[njd][0] = Vw[d * 36 + kkA * 8 + t4];
            b[njd][1] = Vw[d * 36 + kkA * 8 + t4 + 4];
        }
        #pragma unroll
        for (int mi = 0; mi < 2; mi++) {
            uint32_t a[4];
            a[0] = packh2(s[mi][2 * kkA][0],     s[mi][2 * kkA][1]);
            a[1] = packh2(s[mi][2 * kkA][2],     s[mi][2 * kkA][3]);
            a[2] = packh2(s[mi][2 * kkA + 1][0], s[mi][2 * kkA + 1][1]);
            a[3] = packh2(s[mi][2 * kkA + 1][2], s[mi][2 * kkA + 1][3]);
            #pragma unroll
            for (int njd = 0; njd < 4; njd++)
                mma_f16(o[mi][njd], a, b[njd]);
        }
    }

    // ---- store valid rows ----
    #pragma unroll
    for (int mi = 0; mi < 2; mi++) {
        #pragma unroll
        for (int hf = 0; hf < 2; hf++) {
            int row = wh * 32 + mi * 16 + hf * 8 + g4;
            if (row >= NTOK) continue;
            __half* dst = g_hA + ((size_t)(w * NTOK + row)) * DIM + h * HDIM;
            #pragma unroll
            for (int njd = 0; njd < 4; njd++) {
                int d = njd * 8 + 2 * t4;
                *(__half2*)(dst + d) =
                    __floats2half2_rn(o[mi][njd][hf * 2 + 0], o[mi][njd][hf * 2 + 1]);
            }
        }
    }
}

// ---------------- depthwise 3x3 conv + BN + fused LN2 ----------------
__global__ void conv_bn_ln_kernel(const float* __restrict__ w9,
                                  const float* __restrict__ bn_g,
                                  const float* __restrict__ bn_b,
                                  const float* __restrict__ bn_mean,
                                  const float* __restrict__ bn_var,
                                  const float* __restrict__ ln_g,
                                  const float* __restrict__ ln_b) {
    int p = blockIdx.x;
    int bb = p >> 12;
    int pos = p & 4095;
    int r = pos >> 6, c = pos & 63;
    const float* base = g_x1 + (size_t)bb * HW * DIM;
    float o[3];
    #pragma unroll
    for (int k = 0; k < 3; k++) {
        int ch = threadIdx.x + k * 128;
        float s = 0.f;
        #pragma unroll
        for (int kh = 0; kh < 3; kh++) {
            int rr = r + kh - 1;
            if (rr < 0 || rr >= H_) continue;
            #pragma unroll
            for (int kw = 0; kw < 3; kw++) {
                int cc = c + kw - 1;
                if (cc < 0 || cc >= W_) continue;
                s += base[((size_t)rr * W_ + cc) * DIM + ch] * w9[ch * 9 + kh * 3 + kw];
            }
        }
        o[k] = (s - bn_mean[ch]) * rsqrtf(bn_var[ch] + LN_EPS) * bn_g[ch] + bn_b[ch];
        g_x2[(size_t)p * DIM + ch] = o[k];
    }
    float s = o[0] + o[1] + o[2];
    float q = o[0] * o[0] + o[1] * o[1] + o[2] * o[2];
    blockReduce2_128(s, q);
    float mean = s * (1.f / DIM);
    float var = q * (1.f / DIM) - mean * mean;
    float rs = rsqrtf(var + LN_EPS);
    __half* outp = g_hA + (size_t)p * DIM;
    #pragma unroll
    for (int k = 0; k < 3; k++) {
        int ch = threadIdx.x + k * 128;
        outp[ch] = __float2half((o[k] - mean) * rs * ln_g[ch] + ln_b[ch]);
    }
}

// ---------------- launch ----------------
#define ATTN_SMEM (4 * UNIT_HALVES * 2 + 4 * 49 * 4 + 16)
extern "C" void kernel_launch(void* const* d_in, const int* in_sizes, int n_in,
                              void* d_out, int out_size) {
    const float* x       = (const float*)d_in[0];
    const float* ln1_g   = (const float*)d_in[1];
    const float* ln1_b   = (const float*)d_in[2];
    const float* qkv_w   = (const float*)d_in[3];
    const float* qkv_b   = (const float*)d_in[4];
    const float* proj_w  = (const float*)d_in[5];
    const float* proj_b  = (const float*)d_in[6];
    const float* attn_b  = (const float*)d_in[7];
    const float* conv_w  = (const float*)d_in[8];
    const float* bn_g    = (const float*)d_in[9];
    const float* bn_b    = (const float*)d_in[10];
    const float* bn_mean = (const float*)d_in[11];
    const float* bn_var  = (const float*)d_in[12];
    const float* ln2_g   = (const float*)d_in[13];
    const float* ln2_b   = (const float*)d_in[14];
    const float* fc1_w   = (const float*)d_in[15];
    const float* fc1_b   = (const float*)d_in[16];
    const float* fc2_w   = (const float*)d_in[17];
    const float* fc2_b   = (const float*)d_in[18];
    float* out = (float*)d_out;

    __half *phA, *phB, *phW;
    float *px1, *px2;
    cudaGetSymbolAddress((void**)&phA, g_hA);
    cudaGetSymbolAddress((void**)&phB, g_hB);
    cudaGetSymbolAddress((void**)&phW, g_hw);
    cudaGetSymbolAddress((void**)&px1, g_x1);
    cudaGetSymbolAddress((void**)&px2, g_x2);

    cudaFuncSetAttribute(attn_mma, cudaFuncAttributeMaxDynamicSharedMemorySize, ATTN_SMEM);

    // 0. all weight transposes (f32 -> half, (N,K) layout), one launch
    transpose_all<<<1728, dim3(32, 8)>>>(qkv_w, proj_w, fc1_w, fc2_w, phW);

    // 1. LN1 + window partition -> hA (half)
    ln1_win_kernel<<<TOK, 128>>>(x, ln1_g, ln1_b);

    // 2. QKV GEMM -> hB (half)
    mma_gemm<0><<<dim3(1152 / 128, (TOK + 127) / 128), 256>>>(
        phA, phW + WT_QKV_OFF, qkv_b, nullptr, (float*)phB, TOK, 1152, 384);

    // 3. attention (tensor-core) -> hA (half)
    attn_mma<<<NWIN * NHEADS / AUNITS, 256, ATTN_SMEM>>>(attn_b);

    // 4. proj GEMM + un-window + residual -> x1 (f32)
    mma_gemm<1><<<dim3(384 / 128, (TOK + 127) / 128), 256>>>(
        phA, phW + WT_PROJ_OFF, proj_b, x, px1, TOK, 384, 384);

    // 5. depthwise conv + BN -> x2 (f32), fused LN2 -> hA (half)
    conv_bn_ln_kernel<<<BATCH * HW, 128>>>(conv_w, bn_g, bn_b, bn_mean, bn_var,
                                           ln2_g, ln2_b);

    // 6. FC1 + GELU -> hB (half h1)
    mma_gemm<2><<<dim3(1536 / 128, (BATCH * HW) / 128), 256>>>(
        phA, phW + WT_FC1_OFF, fc1_b, nullptr, (float*)phB, BATCH * HW, 1536, 384);

    // 7. FC2 + residual -> d_out (f32)
    mma_gemm<3><<<dim3(384 / 128, (BATCH * HW) / 128), 256>>>(
        phB, phW + WT_FC2_OFF, fc2_b, px2, out, BATCH * HW, 384, 1536);
}